// round 6
// baseline (speedup 1.0000x reference)
#include <cuda_runtime.h>
#include <math.h>

#define M_ROWS 512
#define K_COMP 8
#define B_PTS  4096
#define PHI_DIM 120
#define Z_COLS 80
#define LOG2PI_F 1.8378770664093453f
#define LOG2E_F  1.4426950408889634f

#define NBLK   740            // 148 SMs x 5 CTAs (residency forced by launch_bounds)
#define NCHUNK 32             // chunks per m (128 points each)
#define NTICK  (M_ROWS * NCHUNK)

// Scratch (device globals — no allocation allowed)
__device__ float g_params[M_ROWS][K_COMP][16];   // prepped per-(m,k) coefficients
__device__ float g_zT[72][M_ROWS];               // z columns 0..71, column-major
__device__ float g_respP[NCHUNK][K_COMP][M_ROWS];// per-chunk resp partials
__device__ unsigned g_ticket, g_arrive1, g_arrive2, g_done;

__device__ __forceinline__ float ex2f(float x) {
    float r; asm("ex2.approx.f32 %0, %1;" : "=f"(r) : "f"(x)); return r;
}
__device__ __forceinline__ float rcpf(float x) {
    float r; asm("rcp.approx.f32 %0, %1;" : "=f"(r) : "f"(x)); return r;
}

__device__ __forceinline__ void grid_barrier(unsigned* ctr) {
    __syncthreads();
    if (threadIdx.x == 0) {
        __threadfence();
        atomicAdd(ctr, 1u);
        volatile unsigned* p = ctr;
        while (*p < NBLK) __nanosleep(64);
    }
    __syncthreads();
    __threadfence();
}

// ---------------------------------------------------------------------------
__global__ void __launch_bounds__(128, 5) gmm_all(const float* __restrict__ phi,
                                                  const float4* __restrict__ X,
                                                  float* __restrict__ out) {
    const int tid = threadIdx.x;
    const unsigned lane = tid & 31;
    const int g = lane & 3;          // lane group: handles k = 2g, 2g+1

    // ===================== PHASE 0: prep (4096 (m,k) tasks) =================
    {
        int gid = blockIdx.x * 128 + tid;
        if (gid < M_ROWS * K_COMP) {
            const int m = gid >> 3, k = gid & 7;
            const float* pm = phi + m * PHI_DIM;

            float mx = -INFINITY;
            #pragma unroll
            for (int j = 0; j < K_COMP; j++) mx = fmaxf(mx, pm[j]);
            float s = 0.f;
            #pragma unroll
            for (int j = 0; j < K_COMP; j++) s += __expf(pm[j] - mx);
            float pik = __expf(pm[k] - mx) / s;

            float mu0 = pm[8 + k * 4 + 0];
            float mu1 = pm[8 + k * 4 + 1];
            float mu2 = pm[8 + k * 4 + 2];
            float mu3 = pm[8 + k * 4 + 3];

            const float* lv = pm + 40 + k * 10;
            float L00 = lv[0], L10 = lv[1], L11 = lv[2], L20 = lv[3], L21 = lv[4];
            float L22 = lv[5], L30 = lv[6], L31 = lv[7], L32 = lv[8], L33 = lv[9];

            float G00 = 1.0f / L00, G11 = 1.0f / L11, G22 = 1.0f / L22, G33 = 1.0f / L33;
            float G10 = -L10 * G00 * G11;
            float G21 = -L21 * G11 * G22;
            float G20 = -(L20 * G00 + L21 * G10) * G22;
            float G32 = -L32 * G22 * G33;
            float G31 = -(L31 * G11 + L32 * G21) * G33;
            float G30 = -(L30 * G00 + L31 * G10 + L32 * G20) * G33;

            const float sc = sqrtf(0.5f * LOG2E_F);
            float A00 = sc * G00, A10 = sc * G10, A11 = sc * G11;
            float A20 = sc * G20, A21 = sc * G21, A22 = sc * G22;
            float A30 = sc * G30, A31 = sc * G31, A32 = sc * G32, A33 = sc * G33;

            float* P = g_params[m][k];
            P[0] = A00; P[1] = A10; P[2] = A11; P[3] = A20;
            P[4] = A21; P[5] = A22; P[6] = A30; P[7] = A31;
            P[8] = A32; P[9] = A33;
            P[10] = -(A00 * mu0);
            P[11] = -(A10 * mu0 + A11 * mu1);
            P[12] = -(A20 * mu0 + A21 * mu1 + A22 * mu2);
            P[13] = -(A30 * mu0 + A31 * mu1 + A32 * mu2 + A33 * mu3);

            float log_det = 2.0f * (__logf(fmaxf(fabsf(L00), 1e-8f)) +
                                    __logf(fmaxf(fabsf(L11), 1e-8f)) +
                                    __logf(fmaxf(fabsf(L22), 1e-8f)) +
                                    __logf(fmaxf(fabsf(L33), 1e-8f)));
            float ckv = __logf(fmaxf(pik, 1e-8f)) - 0.5f * (4.0f * LOG2PI_F + log_det);
            P[14] = ckv * LOG2E_F;
            P[15] = 0.f;

            g_zT[k * 4 + 0][m] = mu0;
            g_zT[k * 4 + 1][m] = mu1;
            g_zT[k * 4 + 2][m] = mu2;
            g_zT[k * 4 + 3][m] = mu3;
            g_zT[32 + k * 4 + 0][m] = __logf(fmaxf(fabsf(L00), 1e-6f));
            g_zT[32 + k * 4 + 1][m] = __logf(fmaxf(fabsf(L11), 1e-6f));
            g_zT[32 + k * 4 + 2][m] = __logf(fmaxf(fabsf(L22), 1e-6f));
            g_zT[32 + k * 4 + 3][m] = __logf(fmaxf(fabsf(L33), 1e-6f));
            g_zT[64 + k][m] = pik;
        }
    }

    grid_barrier(&g_arrive1);

    // ===================== PHASE 1: warp-autonomous tickets ==================
    for (;;) {
        unsigned t;
        if (lane == 0) t = atomicAdd(&g_ticket, 1u);
        t = __shfl_sync(0xffffffffu, t, 0);
        if (t >= NTICK) break;
        const int m = t >> 5;
        const int ch = t & (NCHUNK - 1);

        // lane group g loads its two k's coefficients (broadcast across groups)
        const float4* P = (const float4*)g_params[m][2 * g];
        float4 q0 = P[0], q1 = P[1], q2 = P[2], q3 = P[3];  // k0
        float4 q4 = P[4], q5 = P[5], q6 = P[6], q7 = P[7];  // k1

        float acc0 = 0.f, acc1 = 0.f;
        const int pbase = ch * 128 + (int)(lane >> 2);

        #pragma unroll 4
        for (int it = 0; it < 16; it++) {
            float4 x = X[pbase + it * 8];
            // k0
            float a0 = __fmaf_rn(x.x, q0.x, q2.z);
            float a1 = __fmaf_rn(x.x, q0.y, __fmaf_rn(x.y, q0.z, q2.w));
            float a2 = __fmaf_rn(x.x, q0.w,
                       __fmaf_rn(x.y, q1.x, __fmaf_rn(x.z, q1.y, q3.x)));
            float a3 = __fmaf_rn(x.x, q1.z,
                       __fmaf_rn(x.y, q1.w,
                       __fmaf_rn(x.z, q2.x, __fmaf_rn(x.w, q2.y, q3.y))));
            float lj0 = q3.z - __fmaf_rn(a0, a0,
                        __fmaf_rn(a1, a1, __fmaf_rn(a2, a2, a3 * a3)));
            // k1
            float c0 = __fmaf_rn(x.x, q4.x, q6.z);
            float c1 = __fmaf_rn(x.x, q4.y, __fmaf_rn(x.y, q4.z, q6.w));
            float c2 = __fmaf_rn(x.x, q4.w,
                       __fmaf_rn(x.y, q5.x, __fmaf_rn(x.z, q5.y, q7.x)));
            float c3 = __fmaf_rn(x.x, q5.z,
                       __fmaf_rn(x.y, q5.w,
                       __fmaf_rn(x.z, q6.x, __fmaf_rn(x.w, q6.y, q7.y))));
            float lj1 = q7.z - __fmaf_rn(c0, c0,
                        __fmaf_rn(c1, c1, __fmaf_rn(c2, c2, c3 * c3)));

            float mx = fmaxf(lj0, lj1);
            mx = fmaxf(mx, __shfl_xor_sync(0xffffffffu, mx, 1));
            mx = fmaxf(mx, __shfl_xor_sync(0xffffffffu, mx, 2));
            float e0 = ex2f(lj0 - mx);
            float e1 = ex2f(lj1 - mx);
            float s = e0 + e1;
            s += __shfl_xor_sync(0xffffffffu, s, 1);
            s += __shfl_xor_sync(0xffffffffu, s, 2);
            float inv = rcpf(s);
            acc0 = __fmaf_rn(e0, inv, acc0);
            acc1 = __fmaf_rn(e1, inv, acc1);
        }

        // reduce across the 8 point-groups (strides 4,8,16 preserve lane&3)
        acc0 += __shfl_xor_sync(0xffffffffu, acc0, 4);
        acc0 += __shfl_xor_sync(0xffffffffu, acc0, 8);
        acc0 += __shfl_xor_sync(0xffffffffu, acc0, 16);
        acc1 += __shfl_xor_sync(0xffffffffu, acc1, 4);
        acc1 += __shfl_xor_sync(0xffffffffu, acc1, 8);
        acc1 += __shfl_xor_sync(0xffffffffu, acc1, 16);
        if (lane < 4) {
            g_respP[ch][2 * lane + 0][m] = acc0;
            g_respP[ch][2 * lane + 1][m] = acc1;
        }
    }

    grid_barrier(&g_arrive2);

    // ===================== PHASE 2: standardization (blocks 0..79) ===========
    if (blockIdx.x < Z_COLS) {
        const int c = blockIdx.x;
        const unsigned wid = tid >> 5;
        float v[4];
        if (c < 72) {
            const float* col = g_zT[c];
            #pragma unroll
            for (int j = 0; j < 4; j++) v[j] = col[tid + 128 * j];
        } else {
            const int k = c - 72;
            float a[4] = {0.f, 0.f, 0.f, 0.f};
            #pragma unroll 8
            for (int ch = 0; ch < NCHUNK; ch++) {
                #pragma unroll
                for (int j = 0; j < 4; j++) a[j] += g_respP[ch][k][tid + 128 * j];
            }
            #pragma unroll
            for (int j = 0; j < 4; j++) v[j] = a[j] * (1.0f / (float)B_PTS);
        }

        __shared__ float nsh[4];
        __shared__ float n_mean, n_rstd;

        float s = (v[0] + v[1]) + (v[2] + v[3]);
        s += __shfl_down_sync(0xffffffffu, s, 16);
        s += __shfl_down_sync(0xffffffffu, s, 8);
        s += __shfl_down_sync(0xffffffffu, s, 4);
        s += __shfl_down_sync(0xffffffffu, s, 2);
        s += __shfl_down_sync(0xffffffffu, s, 1);
        if (lane == 0) nsh[wid] = s;
        __syncthreads();
        if (tid == 0) n_mean = (nsh[0] + nsh[1] + nsh[2] + nsh[3]) * (1.0f / (float)M_ROWS);
        __syncthreads();
        float mean = n_mean;

        float qsum = 0.f;
        #pragma unroll
        for (int j = 0; j < 4; j++) {
            v[j] -= mean;
            qsum = __fmaf_rn(v[j], v[j], qsum);
        }
        qsum += __shfl_down_sync(0xffffffffu, qsum, 16);
        qsum += __shfl_down_sync(0xffffffffu, qsum, 8);
        qsum += __shfl_down_sync(0xffffffffu, qsum, 4);
        qsum += __shfl_down_sync(0xffffffffu, qsum, 2);
        qsum += __shfl_down_sync(0xffffffffu, qsum, 1);
        __syncthreads();
        if (lane == 0) nsh[wid] = qsum;
        __syncthreads();
        if (tid == 0) {
            float var = (nsh[0] + nsh[1] + nsh[2] + nsh[3]) * (1.0f / (float)(M_ROWS - 1));
            n_rstd = 1.0f / fmaxf(sqrtf(var), 1e-6f);
        }
        __syncthreads();
        float rstd = n_rstd;
        #pragma unroll
        for (int j = 0; j < 4; j++) {
            int r = tid + 128 * j;
            out[r * Z_COLS + c] = v[j] * rstd;
        }
    }

    // ============== counter reset (state -> 0 for graph replay) ==============
    __syncthreads();
    if (tid == 0) {
        __threadfence();
        unsigned d = atomicAdd(&g_done, 1u);
        if (d == NBLK - 1) {
            g_ticket = 0u;
            g_arrive1 = 0u;
            g_arrive2 = 0u;
            g_done = 0u;
            __threadfence();
        }
    }
}

// ---------------------------------------------------------------------------
extern "C" void kernel_launch(void* const* d_in, const int* in_sizes, int n_in,
                              void* d_out, int out_size) {
    const float* phi = (const float*)d_in[0];
    const float4* X = (const float4*)d_in[1];
    float* out = (float*)d_out;

    gmm_all<<<NBLK, 128>>>(phi, X, out);
}

// round 7
// speedup vs baseline: 1.2422x; 1.2422x over previous
#include <cuda_runtime.h>
#include <math.h>

#define M_ROWS 512
#define K_COMP 8
#define B_PTS  4096
#define PHI_DIM 120
#define Z_COLS 80
#define LOG2PI_F 1.8378770664093453f
#define LOG2E_F  1.4426950408889634f

#define NBLK   444        // 148 SMs x 3 CTAs (resident via launch_bounds)
#define NCHUNK 4          // chunks per m, 1024 points each
#define NTICK  (M_ROWS * NCHUNK)

// Scratch (device globals — no allocation allowed)
__device__ float g_par[M_ROWS][120];              // 15 floats per (m,k), k-major
__device__ float g_zT[72][M_ROWS];                // z cols 0..71, column-major
__device__ float g_respP[NCHUNK][K_COMP][M_ROWS]; // per-chunk resp partials
__device__ unsigned g_ticket, g_arrive1, g_arrive2, g_done;

__device__ __forceinline__ float ex2f(float x) {
    float r; asm("ex2.approx.f32 %0, %1;" : "=f"(r) : "f"(x)); return r;
}
__device__ __forceinline__ float rcpf(float x) {
    float r; asm("rcp.approx.f32 %0, %1;" : "=f"(r) : "f"(x)); return r;
}

__device__ __forceinline__ void grid_barrier(unsigned* ctr) {
    __syncthreads();
    if (threadIdx.x == 0) {
        __threadfence();
        atomicAdd(ctr, 1u);
        volatile unsigned* p = ctr;
        while (*p < NBLK) __nanosleep(64);
    }
    __syncthreads();
    __threadfence();
}

// ---------------------------------------------------------------------------
__global__ void __launch_bounds__(128, 3) gmm_all(const float* __restrict__ phi,
                                                  const float4* __restrict__ X,
                                                  float* __restrict__ out) {
    const int tid = threadIdx.x;
    const unsigned lane = tid & 31;
    const unsigned wid = tid >> 5;

    __shared__ float sred[4][K_COMP];
    __shared__ unsigned s_item;

    // ===================== PHASE 0: prep (4096 (m,k) tasks) =================
    {
        int gid = blockIdx.x * 128 + tid;
        if (gid < M_ROWS * K_COMP) {
            const int m = gid >> 3, k = gid & 7;
            const float* pm = phi + m * PHI_DIM;

            float mx = -INFINITY;
            #pragma unroll
            for (int j = 0; j < K_COMP; j++) mx = fmaxf(mx, pm[j]);
            float s = 0.f;
            #pragma unroll
            for (int j = 0; j < K_COMP; j++) s += __expf(pm[j] - mx);
            float pik = __expf(pm[k] - mx) / s;

            float mu0 = pm[8 + k * 4 + 0];
            float mu1 = pm[8 + k * 4 + 1];
            float mu2 = pm[8 + k * 4 + 2];
            float mu3 = pm[8 + k * 4 + 3];

            const float* lv = pm + 40 + k * 10;
            float L00 = lv[0], L10 = lv[1], L11 = lv[2], L20 = lv[3], L21 = lv[4];
            float L22 = lv[5], L30 = lv[6], L31 = lv[7], L32 = lv[8], L33 = lv[9];

            float G00 = 1.0f / L00, G11 = 1.0f / L11, G22 = 1.0f / L22, G33 = 1.0f / L33;
            float G10 = -L10 * G00 * G11;
            float G21 = -L21 * G11 * G22;
            float G20 = -(L20 * G00 + L21 * G10) * G22;
            float G32 = -L32 * G22 * G33;
            float G31 = -(L31 * G11 + L32 * G21) * G33;
            float G30 = -(L30 * G00 + L31 * G10 + L32 * G20) * G33;

            const float sc = sqrtf(0.5f * LOG2E_F);
            float A00 = sc * G00, A10 = sc * G10, A11 = sc * G11;
            float A20 = sc * G20, A21 = sc * G21, A22 = sc * G22;
            float A30 = sc * G30, A31 = sc * G31, A32 = sc * G32, A33 = sc * G33;

            float* P = g_par[m] + k * 15;
            P[0] = A00; P[1] = A10; P[2] = A11; P[3] = A20; P[4] = A21;
            P[5] = A22; P[6] = A30; P[7] = A31; P[8] = A32; P[9] = A33;
            P[10] = -(A00 * mu0);
            P[11] = -(A10 * mu0 + A11 * mu1);
            P[12] = -(A20 * mu0 + A21 * mu1 + A22 * mu2);
            P[13] = -(A30 * mu0 + A31 * mu1 + A32 * mu2 + A33 * mu3);

            float log_det = 2.0f * (__logf(fmaxf(fabsf(L00), 1e-8f)) +
                                    __logf(fmaxf(fabsf(L11), 1e-8f)) +
                                    __logf(fmaxf(fabsf(L22), 1e-8f)) +
                                    __logf(fmaxf(fabsf(L33), 1e-8f)));
            float ckv = __logf(fmaxf(pik, 1e-8f)) - 0.5f * (4.0f * LOG2PI_F + log_det);
            P[14] = ckv * LOG2E_F;

            g_zT[k * 4 + 0][m] = mu0;
            g_zT[k * 4 + 1][m] = mu1;
            g_zT[k * 4 + 2][m] = mu2;
            g_zT[k * 4 + 3][m] = mu3;
            g_zT[32 + k * 4 + 0][m] = __logf(fmaxf(fabsf(L00), 1e-6f));
            g_zT[32 + k * 4 + 1][m] = __logf(fmaxf(fabsf(L11), 1e-6f));
            g_zT[32 + k * 4 + 2][m] = __logf(fmaxf(fabsf(L22), 1e-6f));
            g_zT[32 + k * 4 + 3][m] = __logf(fmaxf(fabsf(L33), 1e-6f));
            g_zT[64 + k][m] = pik;
        }
    }

    grid_barrier(&g_arrive1);

    // ===================== PHASE 1: block-ticketed main loop =================
    for (;;) {
        if (tid == 0) s_item = atomicAdd(&g_ticket, 1u);
        __syncthreads();
        const unsigned item = s_item;
        if (item >= NTICK) break;
        const int m = item >> 2;
        const int ch = item & (NCHUNK - 1);

        // load all 120 params (same for every thread -> broadcast loads)
        float rp[120];
        {
            const float4* P4 = (const float4*)g_par[m];
            #pragma unroll
            for (int j = 0; j < 30; j++) {
                float4 v = P4[j];
                rp[4 * j + 0] = v.x; rp[4 * j + 1] = v.y;
                rp[4 * j + 2] = v.z; rp[4 * j + 3] = v.w;
            }
        }

        float acc[K_COMP];
        #pragma unroll
        for (int k = 0; k < K_COMP; k++) acc[k] = 0.f;

        const int pbase = ch * 1024 + tid;
        #pragma unroll 2
        for (int it = 0; it < 8; it++) {
            float4 x = X[pbase + it * 128];
            float lj[K_COMP];
            #pragma unroll
            for (int k = 0; k < K_COMP; k++) {
                const float* P = rp + k * 15;
                float a0 = __fmaf_rn(x.x, P[0], P[10]);
                float a1 = __fmaf_rn(x.x, P[1], __fmaf_rn(x.y, P[2], P[11]));
                float a2 = __fmaf_rn(x.x, P[3],
                           __fmaf_rn(x.y, P[4], __fmaf_rn(x.z, P[5], P[12])));
                float a3 = __fmaf_rn(x.x, P[6],
                           __fmaf_rn(x.y, P[7],
                           __fmaf_rn(x.z, P[8], __fmaf_rn(x.w, P[9], P[13]))));
                float qq = __fmaf_rn(a0, a0,
                           __fmaf_rn(a1, a1, __fmaf_rn(a2, a2, a3 * a3)));
                lj[k] = P[14] - qq;              // log2 units
            }
            float mx = fmaxf(fmaxf(fmaxf(lj[0], lj[1]), fmaxf(lj[2], lj[3])),
                             fmaxf(fmaxf(lj[4], lj[5]), fmaxf(lj[6], lj[7])));
            float ex[K_COMP];
            #pragma unroll
            for (int k = 0; k < K_COMP; k++) ex[k] = ex2f(lj[k] - mx);
            float s = ((ex[0] + ex[1]) + (ex[2] + ex[3])) +
                      ((ex[4] + ex[5]) + (ex[6] + ex[7]));
            float inv = rcpf(s);
            #pragma unroll
            for (int k = 0; k < K_COMP; k++) acc[k] = __fmaf_rn(ex[k], inv, acc[k]);
        }

        // block reduce
        #pragma unroll
        for (int k = 0; k < K_COMP; k++) {
            float v = acc[k];
            v += __shfl_down_sync(0xffffffffu, v, 16);
            v += __shfl_down_sync(0xffffffffu, v, 8);
            v += __shfl_down_sync(0xffffffffu, v, 4);
            v += __shfl_down_sync(0xffffffffu, v, 2);
            v += __shfl_down_sync(0xffffffffu, v, 1);
            if (lane == 0) sred[wid][k] = v;
        }
        __syncthreads();
        if (tid < K_COMP) {
            g_respP[ch][tid][m] = sred[0][tid] + sred[1][tid] +
                                  sred[2][tid] + sred[3][tid];
        }
        __syncthreads();
    }

    grid_barrier(&g_arrive2);

    // ===================== PHASE 2: standardization (blocks 0..79) ===========
    if (blockIdx.x < Z_COLS) {
        const int c = blockIdx.x;
        float v[4];
        if (c < 72) {
            const float* col = g_zT[c];
            #pragma unroll
            for (int j = 0; j < 4; j++) v[j] = col[tid + 128 * j];
        } else {
            const int k = c - 72;
            #pragma unroll
            for (int j = 0; j < 4; j++) {
                int r = tid + 128 * j;
                v[j] = (g_respP[0][k][r] + g_respP[1][k][r] +
                        g_respP[2][k][r] + g_respP[3][k][r]) * (1.0f / (float)B_PTS);
            }
        }

        __shared__ float nsh[4];
        __shared__ float n_mean, n_rstd;

        float s = (v[0] + v[1]) + (v[2] + v[3]);
        s += __shfl_down_sync(0xffffffffu, s, 16);
        s += __shfl_down_sync(0xffffffffu, s, 8);
        s += __shfl_down_sync(0xffffffffu, s, 4);
        s += __shfl_down_sync(0xffffffffu, s, 2);
        s += __shfl_down_sync(0xffffffffu, s, 1);
        if (lane == 0) nsh[wid] = s;
        __syncthreads();
        if (tid == 0) n_mean = (nsh[0] + nsh[1] + nsh[2] + nsh[3]) * (1.0f / (float)M_ROWS);
        __syncthreads();
        float mean = n_mean;

        float qsum = 0.f;
        #pragma unroll
        for (int j = 0; j < 4; j++) {
            v[j] -= mean;
            qsum = __fmaf_rn(v[j], v[j], qsum);
        }
        qsum += __shfl_down_sync(0xffffffffu, qsum, 16);
        qsum += __shfl_down_sync(0xffffffffu, qsum, 8);
        qsum += __shfl_down_sync(0xffffffffu, qsum, 4);
        qsum += __shfl_down_sync(0xffffffffu, qsum, 2);
        qsum += __shfl_down_sync(0xffffffffu, qsum, 1);
        __syncthreads();
        if (lane == 0) nsh[wid] = qsum;
        __syncthreads();
        if (tid == 0) {
            float var = (nsh[0] + nsh[1] + nsh[2] + nsh[3]) * (1.0f / (float)(M_ROWS - 1));
            n_rstd = 1.0f / fmaxf(sqrtf(var), 1e-6f);
        }
        __syncthreads();
        float rstd = n_rstd;
        #pragma unroll
        for (int j = 0; j < 4; j++) {
            int r = tid + 128 * j;
            out[r * Z_COLS + c] = v[j] * rstd;
        }
    }

    // ============== counter reset (state -> 0 for graph replay) ==============
    __syncthreads();
    if (tid == 0) {
        __threadfence();
        unsigned d = atomicAdd(&g_done, 1u);
        if (d == NBLK - 1) {
            g_ticket = 0u;
            g_arrive1 = 0u;
            g_arrive2 = 0u;
            g_done = 0u;
            __threadfence();
        }
    }
}

// ---------------------------------------------------------------------------
extern "C" void kernel_launch(void* const* d_in, const int* in_sizes, int n_in,
                              void* d_out, int out_size) {
    const float* phi = (const float*)d_in[0];
    const float4* X = (const float4*)d_in[1];
    float* out = (float*)d_out;

    gmm_all<<<NBLK, 128>>>(phi, X, out);
}